// round 12
// baseline (speedup 1.0000x reference)
#include <cuda_runtime.h>
#include <cstdint>

#define HID   16
#define BATCH 2048
#define SEQT  2048
#define FUT   32
#define NOUT  (FUT + 1)
#define WPB   16           // 16 warps = 8 producer/consumer pairs; 128 CTAs -> 1 CTA/SM
#define RING  4

typedef unsigned long long ull;

// ---------- packed f32x2 helpers (sm_103a) ----------
__device__ __forceinline__ ull pack2(float lo, float hi) {
    ull r;
    asm("mov.b64 %0, {%1, %2};" : "=l"(r) : "f"(lo), "f"(hi));
    return r;
}
__device__ __forceinline__ void unpack2(ull v, float& lo, float& hi) {
    asm("mov.b64 {%0, %1}, %2;" : "=f"(lo), "=f"(hi) : "l"(v));
}
__device__ __forceinline__ ull fma2(ull a, ull b, ull c) {
    ull d;
    asm("fma.rn.f32x2 %0, %1, %2, %3;" : "=l"(d) : "l"(a), "l"(b), "l"(c));
    return d;
}
__device__ __forceinline__ float hadd2(ull v) {
    float lo, hi; unpack2(v, lo, hi); return lo + hi;
}

// ---------- fast activations ----------
__device__ __forceinline__ float tanh_ap(float x) {
    float y;
    asm("tanh.approx.f32 %0, %1;" : "=f"(y) : "f"(x));
    return y;
}
__device__ __forceinline__ float sigm(float x) {
    return fmaf(0.5f, tanh_ap(0.5f * x), 0.5f);
}

// ---------- CTA-scope smem release/acquire ----------
__device__ __forceinline__ uint32_t smem_u32(const void* p) {
    return (uint32_t)__cvta_generic_to_shared(p);
}
__device__ __forceinline__ void st_rel(uint32_t addr, int v) {
    asm volatile("st.release.cta.shared.b32 [%0], %1;" :: "r"(addr), "r"(v) : "memory");
}
__device__ __forceinline__ int ld_acq(uint32_t addr) {
    int v;
    asm volatile("ld.acquire.cta.shared.b32 %0, [%1];" : "=r"(v) : "r"(addr) : "memory");
    return v;
}
__device__ __forceinline__ void wait_ge(uint32_t addr, int target) {
    if (ld_acq(addr) >= target) return;
    while (ld_acq(addr) < target) __nanosleep(32);
}

// Warp-specialized pipeline. Warp pair p = (2p: layer-1 producer, 2p+1: layer-2
// consumer). Each pair handles TWO batch elements (lane = e*16 + j). Producer
// publishes h1(t) into a 4-slot smem ring; consumer lags ~1 step. Counters:
// s_prod[p] = producer steps done, s_cons[p] = consumer steps done (incl. head).
// Autoregressive phase: producer waits s_cons >= t and reads o_head.
__global__ void __launch_bounds__(32 * WPB, 1)
lstm_net_kernel(const float* __restrict__ x,
                const float* __restrict__ Wih1, const float* __restrict__ Whh1,
                const float* __restrict__ bih1, const float* __restrict__ bhh1,
                const float* __restrict__ Wih2, const float* __restrict__ Whh2,
                const float* __restrict__ bih2, const float* __restrict__ bhh2,
                const float* __restrict__ fc1w, const float* __restrict__ fc1b,
                const float* __restrict__ fc2w, const float* __restrict__ fc2b,
                float* __restrict__ out)
{
    __shared__ float4 s_ring[WPB / 2][RING][2][4];    // h1 ring [pair][slot][elem][16f]
    __shared__ float4 s_h2b[WPB / 2][2][4];           // h2 broadcast [pair][elem][16f]
    __shared__ ulonglong2 s_w2hif[8][HID];            // Whh2 rows i,f (k-pair packed)
    __shared__ ulonglong2 s_w2hgo[8][HID];            // Whh2 rows g,o
    __shared__ int   s_prod[WPB / 2];
    __shared__ int   s_cons[WPB / 2];
    __shared__ float s_ohead[WPB / 2][2];
    __shared__ float s_fc1w[(HID / 2) * HID];
    __shared__ float s_fc1b[HID / 2];
    __shared__ float s_fc2w[HID / 2];
    __shared__ float s_fc2b;

    const int tid = threadIdx.x;
    if (tid < 128) {
        const int m = tid >> 4, jj = tid & 15;
        s_w2hif[m][jj] = make_ulonglong2(
            pack2(Whh2[jj * HID + 2 * m],        Whh2[jj * HID + 2 * m + 1]),
            pack2(Whh2[(jj + 16) * HID + 2 * m], Whh2[(jj + 16) * HID + 2 * m + 1]));
        s_w2hgo[m][jj] = make_ulonglong2(
            pack2(Whh2[(jj + 32) * HID + 2 * m], Whh2[(jj + 32) * HID + 2 * m + 1]),
            pack2(Whh2[(jj + 48) * HID + 2 * m], Whh2[(jj + 48) * HID + 2 * m + 1]));
    }
    if (tid < (HID / 2) * HID) s_fc1w[tid] = fc1w[tid];
    if (tid < HID / 2) { s_fc1b[tid] = fc1b[tid]; s_fc2w[tid] = fc2w[tid]; }
    if (tid == 0) s_fc2b = fc2b[0];
    if (tid < WPB / 2) { s_prod[tid] = 0; s_cons[tid] = 0; }
    __syncthreads();

    const int lane = tid & 31;
    const int w    = tid >> 5;
    const int pair = w >> 1;
    const bool prod = (w & 1) == 0;
    const int e    = lane >> 4;
    const int j    = lane & 15;
    const int b    = (blockIdx.x * (WPB / 2) + pair) * 2 + e;

    const int r0 = j, r1 = j + HID, r2 = j + 2 * HID, r3 = j + 3 * HID;

    const uint32_t a_prod  = smem_u32(&s_prod[pair]);
    const uint32_t a_cons  = smem_u32(&s_cons[pair]);

    if (prod) {
        // ================= PRODUCER: layer 1 =================
        const float wxi = Wih1[r0], wxf = Wih1[r1], wxg = Wih1[r2], wxo = Wih1[r3];
        const ull pb1i = pack2(bih1[r0] + bhh1[r0], 0.f);
        const ull pb1f = pack2(bih1[r1] + bhh1[r1], 0.f);
        const ull pb1g = pack2(bih1[r2] + bhh1[r2], 0.f);
        const ull pb1o = pack2(bih1[r3] + bhh1[r3], 0.f);

        ull w1i_[8], w1f_[8], w1g_[8], w1o_[8];
#pragma unroll
        for (int m = 0; m < 8; ++m) {
            w1i_[m] = pack2(Whh1[r0 * HID + 2 * m], Whh1[r0 * HID + 2 * m + 1]);
            w1f_[m] = pack2(Whh1[r1 * HID + 2 * m], Whh1[r1 * HID + 2 * m + 1]);
            w1g_[m] = pack2(Whh1[r2 * HID + 2 * m], Whh1[r2 * HID + 2 * m + 1]);
            w1o_[m] = pack2(Whh1[r3 * HID + 2 * m], Whh1[r3 * HID + 2 * m + 1]);
        }

        float c1 = 0.f;
        ull p1i = pb1i, p1f = pb1f, p1g = pb1g, p1o = pb1o;

        const float* xrow = x + (size_t)b * SEQT;
        float xt = xrow[0];

#pragma unroll 1
        for (int t = 0; t < SEQT + FUT; ++t) {
            float inp;
            if (t < SEQT) {
                inp = xt;
                xt = xrow[(t + 1) & (SEQT - 1)];
            } else {
                wait_ge(a_cons, t);            // consumer finished step t-1 (o_head ready)
                inp = s_ohead[pair][e];
            }

            const float ui = fmaf(wxi, inp, hadd2(p1i));
            const float uf = fmaf(wxf, inp, hadd2(p1f));
            const float ug = fmaf(wxg, inp, hadd2(p1g));
            const float uo = fmaf(wxo, inp, hadd2(p1o));
            const float i1 = sigm(ui), f1 = sigm(uf);
            const float g1 = tanh_ap(ug), o1 = sigm(uo);
            c1 = fmaf(f1, c1, i1 * g1);
            const float h1 = o1 * tanh_ap(c1);

            // ring backpressure: slot t&3 last used by step t-4
            if (t >= RING) wait_ge(a_cons, t - (RING - 1));

            float* slot = (float*)&s_ring[pair][t & (RING - 1)][e];
            slot[j] = h1;
            __syncwarp();
            if (lane == 0) st_rel(a_prod, t + 1);

            // pre-accumulate p1 = b1 + Whh1 @ h1 for step t+1
            p1i = pb1i; p1f = pb1f; p1g = pb1g; p1o = pb1o;
            const ulonglong2* hr = (const ulonglong2*)&s_ring[pair][t & (RING - 1)][e];
#pragma unroll
            for (int q = 0; q < 4; ++q) {
                const ulonglong2 hq = hr[q];
                p1i = fma2(w1i_[2 * q], hq.x, p1i);
                p1f = fma2(w1f_[2 * q], hq.x, p1f);
                p1g = fma2(w1g_[2 * q], hq.x, p1g);
                p1o = fma2(w1o_[2 * q], hq.x, p1o);
                p1i = fma2(w1i_[2 * q + 1], hq.y, p1i);
                p1f = fma2(w1f_[2 * q + 1], hq.y, p1f);
                p1g = fma2(w1g_[2 * q + 1], hq.y, p1g);
                p1o = fma2(w1o_[2 * q + 1], hq.y, p1o);
            }
        }
    } else {
        // ================= CONSUMER: layer 2 + head =================
        const ull pb2i = pack2(bih2[r0] + bhh2[r0], 0.f);
        const ull pb2f = pack2(bih2[r1] + bhh2[r1], 0.f);
        const ull pb2g = pack2(bih2[r2] + bhh2[r2], 0.f);
        const ull pb2o = pack2(bih2[r3] + bhh2[r3], 0.f);

        ull w2ii[8], w2if[8], w2ig[8], w2io[8];
#pragma unroll
        for (int m = 0; m < 8; ++m) {
            w2ii[m] = pack2(Wih2[r0 * HID + 2 * m], Wih2[r0 * HID + 2 * m + 1]);
            w2if[m] = pack2(Wih2[r1 * HID + 2 * m], Wih2[r1 * HID + 2 * m + 1]);
            w2ig[m] = pack2(Wih2[r2 * HID + 2 * m], Wih2[r2 * HID + 2 * m + 1]);
            w2io[m] = pack2(Wih2[r3 * HID + 2 * m], Wih2[r3 * HID + 2 * m + 1]);
        }

        float c2 = 0.f;
        ull p2i = pack2(0.f, 0.f), p2f = p2i, p2g = p2i, p2o = p2i;

        float* s_h2me = (float*)&s_h2b[pair][e];
        const ulonglong2* h2rd = (const ulonglong2*)&s_h2b[pair][e];
        float* orow = out + (size_t)b * NOUT;

#pragma unroll 1
        for (int t = 0; t < SEQT + FUT; ++t) {
            wait_ge(a_prod, t + 1);            // h1(t) published

            ull a2i = pb2i, a2f = pb2f, a2g = pb2g, a2o = pb2o;
            const ulonglong2* hr = (const ulonglong2*)&s_ring[pair][t & (RING - 1)][e];
#pragma unroll
            for (int q = 0; q < 4; ++q) {
                const ulonglong2 hq = hr[q];
                a2i = fma2(w2ii[2 * q], hq.x, a2i);
                a2f = fma2(w2if[2 * q], hq.x, a2f);
                a2g = fma2(w2ig[2 * q], hq.x, a2g);
                a2o = fma2(w2io[2 * q], hq.x, a2o);
                a2i = fma2(w2ii[2 * q + 1], hq.y, a2i);
                a2f = fma2(w2if[2 * q + 1], hq.y, a2f);
                a2g = fma2(w2ig[2 * q + 1], hq.y, a2g);
                a2o = fma2(w2io[2 * q + 1], hq.y, a2o);
            }

            const float vi = hadd2(a2i) + hadd2(p2i);
            const float vf = hadd2(a2f) + hadd2(p2f);
            const float vg = hadd2(a2g) + hadd2(p2g);
            const float vo = hadd2(a2o) + hadd2(p2o);
            const float i2 = sigm(vi), f2 = sigm(vf);
            const float g2 = tanh_ap(vg), o2 = sigm(vo);
            c2 = fmaf(f2, c2, i2 * g2);
            const float h2 = o2 * tanh_ap(c2);

            s_h2me[j] = h2;
            __syncwarp();

            // p2 = Whh2 @ h2 (weights from smem; slack-rich loop)
            p2i = pack2(0.f, 0.f); p2f = p2i; p2g = p2i; p2o = p2i;
#pragma unroll
            for (int q = 0; q < 4; ++q) {
                const ulonglong2 hq = h2rd[q];
                const ulonglong2 wif0 = s_w2hif[2 * q][j];
                const ulonglong2 wgo0 = s_w2hgo[2 * q][j];
                const ulonglong2 wif1 = s_w2hif[2 * q + 1][j];
                const ulonglong2 wgo1 = s_w2hgo[2 * q + 1][j];
                p2i = fma2(wif0.x, hq.x, p2i);
                p2f = fma2(wif0.y, hq.x, p2f);
                p2g = fma2(wgo0.x, hq.x, p2g);
                p2o = fma2(wgo0.y, hq.x, p2o);
                p2i = fma2(wif1.x, hq.y, p2i);
                p2f = fma2(wif1.y, hq.y, p2f);
                p2g = fma2(wgo1.x, hq.y, p2g);
                p2o = fma2(wgo1.y, hq.y, p2o);
            }

            // head (last teacher step + future steps)
            if (t >= SEQT - 1) {
                const int jj = j & 7;
                float acc = s_fc1b[jj];
#pragma unroll
                for (int k = 0; k < HID; ++k)
                    acc = fmaf(s_fc1w[jj * HID + k], s_h2me[k], acc);
                acc = (acc >= 0.f) ? acc : 0.2f * acc;     // LeakyReLU(0.2)
                float p = (j < 8) ? s_fc2w[jj] * acc : 0.f;
                p += __shfl_xor_sync(0xffffffffu, p, 8);
                p += __shfl_xor_sync(0xffffffffu, p, 4);
                p += __shfl_xor_sync(0xffffffffu, p, 2);
                p += __shfl_xor_sync(0xffffffffu, p, 1);
                const float oh = p + s_fc2b;
                if (j == 0) {
                    s_ohead[pair][e] = oh;
                    orow[t - (SEQT - 1)] = oh;
                }
            }

            __syncwarp();
            if (lane == 0) st_rel(a_cons, t + 1);
        }
    }
}

extern "C" void kernel_launch(void* const* d_in, const int* in_sizes, int n_in,
                              void* d_out, int out_size)
{
    const float* x    = (const float*)d_in[0];
    const float* Wih1 = (const float*)d_in[1];
    const float* Whh1 = (const float*)d_in[2];
    const float* bih1 = (const float*)d_in[3];
    const float* bhh1 = (const float*)d_in[4];
    const float* Wih2 = (const float*)d_in[5];
    const float* Whh2 = (const float*)d_in[6];
    const float* bih2 = (const float*)d_in[7];
    const float* bhh2 = (const float*)d_in[8];
    const float* fc1w = (const float*)d_in[9];
    const float* fc1b = (const float*)d_in[10];
    const float* fc2w = (const float*)d_in[11];
    const float* fc2b = (const float*)d_in[12];
    float* out = (float*)d_out;

    // 128 blocks x 512 threads: 1 CTA/SM; 8 producer+8 consumer warps per CTA,
    // 16 batch elements per CTA (2 per warp pair).
    lstm_net_kernel<<<BATCH / 16, 32 * WPB>>>(x, Wih1, Whh1, bih1, bhh1,
                                              Wih2, Whh2, bih2, bhh2,
                                              fc1w, fc1b, fc2w, fc2b, out);
}

// round 13
// speedup vs baseline: 1.4955x; 1.4955x over previous
#include <cuda_runtime.h>
#include <cstdint>

#define HID   16
#define BATCH 2048
#define SEQT  2048
#define FUT   32
#define NOUT  (FUT + 1)
#define WPB   8            // 8 warps/CTA, 128 CTAs -> 1 CTA/SM, 2 warps/SMSP uniform

typedef unsigned long long ull;

// ---------- packed f32x2 helpers (sm_103a) ----------
__device__ __forceinline__ ull pack2(float lo, float hi) {
    ull r;
    asm("mov.b64 %0, {%1, %2};" : "=l"(r) : "f"(lo), "f"(hi));
    return r;
}
__device__ __forceinline__ void unpack2(ull v, float& lo, float& hi) {
    asm("mov.b64 {%0, %1}, %2;" : "=f"(lo), "=f"(hi) : "l"(v));
}
__device__ __forceinline__ ull fma2(ull a, ull b, ull c) {
    ull d;
    asm("fma.rn.f32x2 %0, %1, %2, %3;" : "=l"(d) : "l"(a), "l"(b), "l"(c));
    return d;
}
__device__ __forceinline__ ull add2(ull a, ull b) {
    ull d;
    asm("add.rn.f32x2 %0, %1, %2;" : "=l"(d) : "l"(a), "l"(b));
    return d;
}
__device__ __forceinline__ float hadd2(ull v) {
    float lo, hi; unpack2(v, lo, hi); return lo + hi;
}

// ---------- fast activations ----------
__device__ __forceinline__ float tanh_ap(float x) {
    float y;
    asm("tanh.approx.f32 %0, %1;" : "=f"(y) : "f"(x));
    return y;
}
__device__ __forceinline__ float sigm(float x) {
    return fmaf(0.5f, tanh_ap(0.5f * x), 0.5f);
}

// One warp = TWO batch elements (lane = e*16 + j); lane owns all 4 gate rows
// of unit j. Whh1 + Wih2 + Whh2(i,f) weights in registers; Whh2(g,o) in smem.
// PHASE-STAGGERED: warps (w, w+4) share an SMSP (wid%4). Phase-0 warps run the
// body [L1(t); L2(t)]; phase-1 warps peel L1(0) and run [L2(t); L1(t+1)], so
// the two co-resident warps execute complementary segments (fma2-dense matvec
// vs MUFU-dense gates) instead of colliding in lockstep.
__global__ void __launch_bounds__(32 * WPB, 1)
lstm_net_kernel(const float* __restrict__ x,
                const float* __restrict__ Wih1, const float* __restrict__ Whh1,
                const float* __restrict__ bih1, const float* __restrict__ bhh1,
                const float* __restrict__ Wih2, const float* __restrict__ Whh2,
                const float* __restrict__ bih2, const float* __restrict__ bhh2,
                const float* __restrict__ fc1w, const float* __restrict__ fc1b,
                const float* __restrict__ fc2w, const float* __restrict__ fc2b,
                float* __restrict__ out)
{
    __shared__ ulonglong2 s_w2hgo[8][HID];     // Whh2 g/o rows, k-pair packed
    __shared__ float4 s_h1[WPB][2][4];         // h1 broadcast [warp][elem][16f]
    __shared__ float4 s_h2[WPB][2][4];         // h2 broadcast
    __shared__ float s_fc1w[(HID / 2) * HID];
    __shared__ float s_fc1b[HID / 2];
    __shared__ float s_fc2w[HID / 2];
    __shared__ float s_fc2b;

    const int tid = threadIdx.x;
    if (tid < 128) {
        const int m = tid >> 4, jj = tid & 15;
        s_w2hgo[m][jj] = make_ulonglong2(
            pack2(Whh2[(jj + 32) * HID + 2 * m], Whh2[(jj + 32) * HID + 2 * m + 1]),
            pack2(Whh2[(jj + 48) * HID + 2 * m], Whh2[(jj + 48) * HID + 2 * m + 1]));
    }
    if (tid < (HID / 2) * HID) s_fc1w[tid] = fc1w[tid];
    if (tid < HID / 2) { s_fc1b[tid] = fc1b[tid]; s_fc2w[tid] = fc2w[tid]; }
    if (tid == 0) s_fc2b = fc2b[0];
    __syncthreads();

    const int lane = tid & 31;
    const int w    = tid >> 5;
    const int e    = lane >> 4;
    const int j    = lane & 15;
    const int b    = (blockIdx.x * WPB + w) * 2 + e;
    const bool ph1 = (w & 4) != 0;             // SMSP partner of a phase-0 warp

    const int r0 = j, r1 = j + HID, r2 = j + 2 * HID, r3 = j + 3 * HID;

    const float wxi = Wih1[r0], wxf = Wih1[r1], wxg = Wih1[r2], wxo = Wih1[r3];
    const ull pb1i = pack2(bih1[r0] + bhh1[r0], 0.f);
    const ull pb1f = pack2(bih1[r1] + bhh1[r1], 0.f);
    const ull pb1g = pack2(bih1[r2] + bhh1[r2], 0.f);
    const ull pb1o = pack2(bih1[r3] + bhh1[r3], 0.f);
    const ull pb2i = pack2(bih2[r0] + bhh2[r0], 0.f);
    const ull pb2f = pack2(bih2[r1] + bhh2[r1], 0.f);
    const ull pb2g = pack2(bih2[r2] + bhh2[r2], 0.f);
    const ull pb2o = pack2(bih2[r3] + bhh2[r3], 0.f);

    // register weights (k-pair packed): 10 arrays x 8 ull = 160 regs
    ull w1i_[8], w1f_[8], w1g_[8], w1o_[8];    // Whh1
    ull w2ii[8], w2if[8], w2ig[8], w2io[8];    // Wih2
    ull w2hi[8], w2hf[8];                      // Whh2 i/f rows
#pragma unroll
    for (int m = 0; m < 8; ++m) {
        w1i_[m] = pack2(Whh1[r0 * HID + 2 * m], Whh1[r0 * HID + 2 * m + 1]);
        w1f_[m] = pack2(Whh1[r1 * HID + 2 * m], Whh1[r1 * HID + 2 * m + 1]);
        w1g_[m] = pack2(Whh1[r2 * HID + 2 * m], Whh1[r2 * HID + 2 * m + 1]);
        w1o_[m] = pack2(Whh1[r3 * HID + 2 * m], Whh1[r3 * HID + 2 * m + 1]);
        w2ii[m] = pack2(Wih2[r0 * HID + 2 * m], Wih2[r0 * HID + 2 * m + 1]);
        w2if[m] = pack2(Wih2[r1 * HID + 2 * m], Wih2[r1 * HID + 2 * m + 1]);
        w2ig[m] = pack2(Wih2[r2 * HID + 2 * m], Wih2[r2 * HID + 2 * m + 1]);
        w2io[m] = pack2(Wih2[r3 * HID + 2 * m], Wih2[r3 * HID + 2 * m + 1]);
        w2hi[m] = pack2(Whh2[r0 * HID + 2 * m], Whh2[r0 * HID + 2 * m + 1]);
        w2hf[m] = pack2(Whh2[r1 * HID + 2 * m], Whh2[r1 * HID + 2 * m + 1]);
    }

    // carried state
    float c1 = 0.f, c2 = 0.f, o_head = 0.f;
    ull p1i = pb1i, p1f = pb1f, p1g = pb1g, p1o = pb1o;     // b1 + Whh1@h1_prev
    ull p2i = pack2(0.f, 0.f), p2f = p2i, p2g = p2i, p2o = p2i;  // Whh2@h2_prev
    ull s2i = p2i, s2f = p2i, s2g = p2i, s2o = p2i;         // a2 + p2 (layer-2 input)

    float* s_h1me = (float*)&s_h1[w][e];
    float* s_h2me = (float*)&s_h2[w][e];
    const ulonglong2* h1rd = (const ulonglong2*)&s_h1[w][e];
    const ulonglong2* h2rd = (const ulonglong2*)&s_h2[w][e];

    const float* xrow = x + (size_t)b * SEQT;
    float* orow = out + (size_t)b * NOUT;
    float xt = xrow[0];

    // ---- step segments as lambdas (fully inlined) ----
    auto layer1 = [&](float inp) -> float {
        const float ui = fmaf(wxi, inp, hadd2(p1i));
        const float uf = fmaf(wxf, inp, hadd2(p1f));
        const float ug = fmaf(wxg, inp, hadd2(p1g));
        const float uo = fmaf(wxo, inp, hadd2(p1o));
        const float i1 = sigm(ui), f1 = sigm(uf);
        const float g1 = tanh_ap(ug), o1 = sigm(uo);
        c1 = fmaf(f1, c1, i1 * g1);
        return o1 * tanh_ap(c1);
    };

    // broadcast h1; compute a2 = b2 + Wih2@h1, p1 = b1 + Whh1@h1, s2 = a2 + p2
    auto bcast_combined = [&](float h1) {
        s_h1me[j] = h1;
        __syncwarp();
        ull a2i = pb2i, a2f = pb2f, a2g = pb2g, a2o = pb2o;
        p1i = pb1i; p1f = pb1f; p1g = pb1g; p1o = pb1o;
#pragma unroll
        for (int q = 0; q < 4; ++q) {
            const ulonglong2 hq = h1rd[q];
            a2i = fma2(w2ii[2 * q], hq.x, a2i);
            a2f = fma2(w2if[2 * q], hq.x, a2f);
            a2g = fma2(w2ig[2 * q], hq.x, a2g);
            a2o = fma2(w2io[2 * q], hq.x, a2o);
            p1i = fma2(w1i_[2 * q], hq.x, p1i);
            p1f = fma2(w1f_[2 * q], hq.x, p1f);
            p1g = fma2(w1g_[2 * q], hq.x, p1g);
            p1o = fma2(w1o_[2 * q], hq.x, p1o);
            a2i = fma2(w2ii[2 * q + 1], hq.y, a2i);
            a2f = fma2(w2if[2 * q + 1], hq.y, a2f);
            a2g = fma2(w2ig[2 * q + 1], hq.y, a2g);
            a2o = fma2(w2io[2 * q + 1], hq.y, a2o);
            p1i = fma2(w1i_[2 * q + 1], hq.y, p1i);
            p1f = fma2(w1f_[2 * q + 1], hq.y, p1f);
            p1g = fma2(w1g_[2 * q + 1], hq.y, p1g);
            p1o = fma2(w1o_[2 * q + 1], hq.y, p1o);
        }
        s2i = add2(a2i, p2i); s2f = add2(a2f, p2f);
        s2g = add2(a2g, p2g); s2o = add2(a2o, p2o);
    };

    auto layer2 = [&]() -> float {
        const float vi = hadd2(s2i), vf = hadd2(s2f);
        const float vg = hadd2(s2g), vo = hadd2(s2o);
        const float i2 = sigm(vi), f2 = sigm(vf);
        const float g2 = tanh_ap(vg), o2 = sigm(vo);
        c2 = fmaf(f2, c2, i2 * g2);
        return o2 * tanh_ap(c2);
    };

    // broadcast h2; p2 = Whh2 @ h2 (i/f rows from regs, g/o rows from smem)
    auto bcast_p2 = [&](float h2) {
        s_h2me[j] = h2;
        __syncwarp();
        p2i = pack2(0.f, 0.f); p2f = p2i; p2g = p2i; p2o = p2i;
#pragma unroll
        for (int q = 0; q < 4; ++q) {
            const ulonglong2 hq = h2rd[q];
            const ulonglong2 wgo0 = s_w2hgo[2 * q][j];
            const ulonglong2 wgo1 = s_w2hgo[2 * q + 1][j];
            p2i = fma2(w2hi[2 * q], hq.x, p2i);
            p2f = fma2(w2hf[2 * q], hq.x, p2f);
            p2g = fma2(wgo0.x, hq.x, p2g);
            p2o = fma2(wgo0.y, hq.x, p2o);
            p2i = fma2(w2hi[2 * q + 1], hq.y, p2i);
            p2f = fma2(w2hf[2 * q + 1], hq.y, p2f);
            p2g = fma2(wgo1.x, hq.y, p2g);
            p2o = fma2(wgo1.y, hq.y, p2o);
        }
    };

    auto head = [&](int t) {
        if (t >= SEQT - 1) {
            const int jj = j & 7;
            float acc = s_fc1b[jj];
#pragma unroll
            for (int k = 0; k < HID; ++k)
                acc = fmaf(s_fc1w[jj * HID + k], s_h2me[k], acc);
            acc = (acc >= 0.f) ? acc : 0.2f * acc;      // LeakyReLU(0.2)
            float p = (j < 8) ? s_fc2w[jj] * acc : 0.f;
            p += __shfl_xor_sync(0xffffffffu, p, 8);
            p += __shfl_xor_sync(0xffffffffu, p, 4);
            p += __shfl_xor_sync(0xffffffffu, p, 2);
            p += __shfl_xor_sync(0xffffffffu, p, 1);
            o_head = p + s_fc2b;
            if (j == 0) orow[t - (SEQT - 1)] = o_head;
        }
    };

    if (!ph1) {
        // ===== phase 0: body = [L1(t); L2(t)] =====
#pragma unroll 1
        for (int t = 0; t < SEQT + FUT; ++t) {
            const float inp = (t < SEQT) ? xt : o_head;
            xt = xrow[(t + 1) & (SEQT - 1)];
            const float h1 = layer1(inp);
            bcast_combined(h1);
            const float h2 = layer2();
            bcast_p2(h2);
            head(t);
        }
    } else {
        // ===== phase 1: peel L1(0); body = [L2(t); L1(t+1)] =====
        {
            const float inp0 = xt;                      // x[0]
            xt = xrow[1];
            const float h1 = layer1(inp0);
            bcast_combined(h1);                         // s2 for t=0 (p2=0)
        }
#pragma unroll 1
        for (int t = 0; t < SEQT + FUT; ++t) {
            const float h2 = layer2();                  // step t
            bcast_p2(h2);
            head(t);
            // layer 1 of step t+1 (last iteration's is harmless extra work)
            const float inp = (t + 1 < SEQT) ? xt : o_head;
            xt = xrow[(t + 2) & (SEQT - 1)];
            const float h1 = layer1(inp);
            bcast_combined(h1);
        }
    }
}

extern "C" void kernel_launch(void* const* d_in, const int* in_sizes, int n_in,
                              void* d_out, int out_size)
{
    const float* x    = (const float*)d_in[0];
    const float* Wih1 = (const float*)d_in[1];
    const float* Whh1 = (const float*)d_in[2];
    const float* bih1 = (const float*)d_in[3];
    const float* bhh1 = (const float*)d_in[4];
    const float* Wih2 = (const float*)d_in[5];
    const float* Whh2 = (const float*)d_in[6];
    const float* bih2 = (const float*)d_in[7];
    const float* bhh2 = (const float*)d_in[8];
    const float* fc1w = (const float*)d_in[9];
    const float* fc1b = (const float*)d_in[10];
    const float* fc2w = (const float*)d_in[11];
    const float* fc2b = (const float*)d_in[12];
    float* out = (float*)d_out;

    // 128 blocks x 256 threads: 1 CTA/SM, exactly 2 warps/SMSP everywhere;
    // co-resident warp pairs (w, w+4) run phase-staggered loop bodies.
    lstm_net_kernel<<<BATCH / 16, 32 * WPB>>>(x, Wih1, Whh1, bih1, bhh1,
                                              Wih2, Whh2, bih2, bhh2,
                                              fc1w, fc1b, fc2w, fc2b, out);
}